// round 1
// baseline (speedup 1.0000x reference)
#include <cuda_runtime.h>
#include <cuda_bf16.h>

// Problem constants
#define NN 50000
#define EE 1600000
#define GG 512
#define INF_ 128
#define HID 128
#define PROJ 256

// ---------------- device scratch (static, no allocation) ----------------
__device__ float g_G[NN * HID];      // GEMM output (pre-aggregation)
__device__ float g_Ha[NN * HID];     // h buffers (ping-pong)
__device__ float g_Hb[NN * HID];
__device__ float g_dinv[NN];
__device__ int   g_cnt[NN];          // degree counts -> cursor
__device__ int   g_off[NN + 1];      // CSR offsets
__device__ int   g_csr[EE];          // CSR src ids
__device__ int   g_gs[GG];           // graph start
__device__ int   g_ge[GG];           // graph end
__device__ float g_pool[2 * GG * HID];
__device__ float g_t [GG * PROJ];
__device__ float g_t2[GG * PROJ];
__device__ float g_q [GG * (PROJ/2)];

// ---------------- helpers ----------------
__global__ void k_zero(int n, int g) {
    int i = blockIdx.x * blockDim.x + threadIdx.x;
    if (i < n) g_cnt[i] = 0;
    if (i < g) { g_gs[i] = n; g_ge[i] = 0; }
}

__global__ void k_degree(const int* __restrict__ dst, int e) {
    int i = blockIdx.x * blockDim.x + threadIdx.x;
    if (i < e) atomicAdd(&g_cnt[dst[i]], 1);
}

__global__ void k_dinv(int n) {
    int i = blockIdx.x * blockDim.x + threadIdx.x;
    if (i < n) g_dinv[i] = 1.0f / sqrtf((float)(g_cnt[i] + 1)); // +1 self loop
}

// single-block exclusive scan of g_cnt -> g_off (and g_cnt becomes cursor copy)
__global__ void k_scan(int n) {
    __shared__ int warpsums[32];
    __shared__ int s_carry;
    int tid = threadIdx.x, lane = tid & 31, wid = tid >> 5;
    int nwarps = blockDim.x >> 5;
    if (tid == 0) s_carry = 0;
    __syncthreads();
    for (int base = 0; base < n; base += blockDim.x) {
        int i = base + tid;
        int v = (i < n) ? g_cnt[i] : 0;
        int x = v;
        #pragma unroll
        for (int d = 1; d < 32; d <<= 1) {
            int y = __shfl_up_sync(0xffffffffu, x, d);
            if (lane >= d) x += y;
        }
        if (lane == 31) warpsums[wid] = x;
        __syncthreads();
        if (wid == 0) {
            int s = (lane < nwarps) ? warpsums[lane] : 0;
            #pragma unroll
            for (int d = 1; d < 32; d <<= 1) {
                int y = __shfl_up_sync(0xffffffffu, s, d);
                if (lane >= d) s += y;
            }
            warpsums[lane] = s;
        }
        __syncthreads();
        int warpoff = (wid == 0) ? 0 : warpsums[wid - 1];
        int carry = s_carry;
        int total = warpsums[nwarps - 1];
        int excl = x + warpoff - v + carry;
        if (i < n) { g_off[i] = excl; g_cnt[i] = excl; }
        __syncthreads();
        if (tid == 0) s_carry = carry + total;
        __syncthreads();
    }
    if (tid == 0) g_off[n] = s_carry;
}

__global__ void k_fill(const int* __restrict__ src, const int* __restrict__ dst, int e) {
    int i = blockIdx.x * blockDim.x + threadIdx.x;
    if (i < e) {
        int d = dst[i];
        int pos = atomicAdd(&g_cnt[d], 1);
        g_csr[pos] = src[i];
    }
}

// ---------------- big GEMM: out[M,128] = A[M,128] @ W[128,128] ----------------
// dynamic smem: W (64KB) + A-tile (32KB)
__global__ void k_gemm_big(const float4* __restrict__ A, const float4* __restrict__ W,
                           float4* __restrict__ out, int M) {
    extern __shared__ float sm[];
    float4* Ws4 = (float4*)sm;           // [128*32]
    float4* As4 = (float4*)(sm + 128 * 128);  // [64*32]
    const float* As = sm + 128 * 128;
    int tid = threadIdx.x;
    for (int i = tid; i < 128 * 32; i += 256) Ws4[i] = W[i];
    int rowbase = blockIdx.x * 64;
    for (int i = tid; i < 64 * 32; i += 256) {
        int r = rowbase + (i >> 5);
        float4 v = make_float4(0.f, 0.f, 0.f, 0.f);
        if (r < M) v = A[r * 32 + (i & 31)];
        As4[i] = v;
    }
    __syncthreads();
    int lane = tid & 31, w = tid >> 5;
    float4 acc[8];
    #pragma unroll
    for (int r = 0; r < 8; r++) acc[r] = make_float4(0.f, 0.f, 0.f, 0.f);
    #pragma unroll 8
    for (int k = 0; k < 128; k++) {
        float4 wv = Ws4[k * 32 + lane];
        #pragma unroll
        for (int r = 0; r < 8; r++) {
            float av = As[(w + r * 8) * 128 + k];
            acc[r].x += av * wv.x; acc[r].y += av * wv.y;
            acc[r].z += av * wv.z; acc[r].w += av * wv.w;
        }
    }
    #pragma unroll
    for (int r = 0; r < 8; r++) {
        int row = rowbase + w + r * 8;
        if (row < M) out[row * 32 + lane] = acc[r];
    }
}

// ---------------- gather: warp per node ----------------
// out[v] = act( dinv[v] * (sum_u dinv[u]*B[u] + dinv[v]*B[v]) + bias ) [+ residual]
__global__ void k_gather(const float4* __restrict__ B, const float* __restrict__ bias,
                         const float4* __restrict__ Hres, float4* __restrict__ out,
                         int n, int mode) {
    int gw = (blockIdx.x * blockDim.x + threadIdx.x) >> 5;
    if (gw >= n) return;
    int lane = threadIdx.x & 31;
    int v = gw;
    int off0 = g_off[v], off1 = g_off[v + 1];
    float dv = g_dinv[v];
    float4 bv = B[v * 32 + lane];
    float4 acc = make_float4(dv * bv.x, dv * bv.y, dv * bv.z, dv * bv.w);
    for (int j = off0; j < off1; j += 32) {
        int idx = j + lane;
        int u = (idx < off1) ? g_csr[idx] : -1;
        float wt = (u >= 0) ? g_dinv[u] : 0.f;
        int m = off1 - j; if (m > 32) m = 32;
        #pragma unroll 4
        for (int i = 0; i < m; i++) {
            int uu = __shfl_sync(0xffffffffu, u, i);
            float ww = __shfl_sync(0xffffffffu, wt, i);
            float4 hv = B[uu * 32 + lane];
            acc.x += ww * hv.x; acc.y += ww * hv.y;
            acc.z += ww * hv.z; acc.w += ww * hv.w;
        }
    }
    const float4* b4 = (const float4*)bias;
    float4 bb = b4[lane];
    float4 r;
    r.x = fmaxf(dv * acc.x + bb.x, 0.f);
    r.y = fmaxf(dv * acc.y + bb.y, 0.f);
    r.z = fmaxf(dv * acc.z + bb.z, 0.f);
    r.w = fmaxf(dv * acc.w + bb.w, 0.f);
    if (mode == 1) {
        float4 h = Hres[v * 32 + lane];
        r.x += h.x; r.y += h.y; r.z += h.z; r.w += h.w;
    }
    out[v * 32 + lane] = r;
}

// ---------------- pooling ----------------
__global__ void k_bounds(const int* __restrict__ batch, int n) {
    int i = blockIdx.x * blockDim.x + threadIdx.x;
    if (i >= n) return;
    int b = batch[i];
    if (i == 0 || batch[i - 1] != b) g_gs[b] = i;
    if (i == n - 1 || batch[i + 1] != b) g_ge[b] = i + 1;
}

__global__ void k_pool(const float4* __restrict__ H, float4* __restrict__ pool, int g) {
    int gw = (blockIdx.x * blockDim.x + threadIdx.x) >> 5;
    if (gw >= g) return;
    int lane = threadIdx.x & 31;
    int s = g_gs[gw], e = g_ge[gw];
    float4 acc = make_float4(0.f, 0.f, 0.f, 0.f);
    for (int r = s; r < e; r++) {
        float4 v = H[r * 32 + lane];
        acc.x += v.x; acc.y += v.y; acc.z += v.z; acc.w += v.w;
    }
    float sc = (e > s) ? 1.0f / (float)(e - s) : 0.f;
    pool[gw * 32 + lane] = make_float4(acc.x * sc, acc.y * sc, acc.z * sc, acc.w * sc);
}

// ---------------- small GEMM: warp per row ----------------
template <int NPER>
__global__ void k_gemm_small(const float* __restrict__ A, const float* __restrict__ W,
                             const float* __restrict__ bias, float* __restrict__ out,
                             int M, int K, int N, int relu) {
    int gw = (blockIdx.x * blockDim.x + threadIdx.x) >> 5;
    if (gw >= M) return;
    int lane = threadIdx.x & 31;
    float acc[NPER];
    #pragma unroll
    for (int j = 0; j < NPER; j++) acc[j] = 0.f;
    const float* a = A + gw * K;
    for (int k = 0; k < K; k++) {
        float av = __ldg(a + k);
        const float* wr = W + k * N;
        #pragma unroll
        for (int j = 0; j < NPER; j++) acc[j] += av * __ldg(wr + lane + 32 * j);
    }
    #pragma unroll
    for (int j = 0; j < NPER; j++) {
        float v = acc[j] + bias[lane + 32 * j];
        if (relu) v = fmaxf(v, 0.f);
        out[gw * N + lane + 32 * j] = v;
    }
}

// ---------------- batchnorm: block per column, rows fixed ----------------
__global__ void k_bn(const float* __restrict__ x, const float* __restrict__ gamma,
                     const float* __restrict__ beta, float* __restrict__ out,
                     int rows, int cols, int relu) {
    int col = blockIdx.x;
    int tid = threadIdx.x, lane = tid & 31, wid = tid >> 5;
    __shared__ float red[8];
    __shared__ float s_m, s_inv;
    float s = 0.f, s2 = 0.f;
    for (int r = tid; r < rows; r += blockDim.x) {
        float v = x[r * cols + col];
        s += v; s2 += v * v;
    }
    #pragma unroll
    for (int o = 16; o; o >>= 1) {
        s  += __shfl_down_sync(0xffffffffu, s, o);
        s2 += __shfl_down_sync(0xffffffffu, s2, o);
    }
    if (lane == 0) { red[wid] = s; red[4 + wid] = s2; }
    __syncthreads();
    if (tid == 0) {
        float ts = red[0] + red[1] + red[2] + red[3];
        float t2 = red[4] + red[5] + red[6] + red[7];
        float m = ts / rows;
        float var = t2 / rows - m * m;
        s_m = m;
        s_inv = rsqrtf(var + 1e-5f);
    }
    __syncthreads();
    float m = s_m, inv = s_inv, ga = gamma[col], be = beta[col];
    for (int r = tid; r < rows; r += blockDim.x) {
        float v = ga * (x[r * cols + col] - m) * inv + be;
        if (relu) v = fmaxf(v, 0.f);
        out[r * cols + col] = v;
    }
}

// ---------------- host orchestration ----------------
static void run_encoder(const float* x, const int* ei, const int* batch,
                        const float* W1, const float* b1,
                        const float* W2, const float* b2,
                        const float* W3, const float* b3,
                        float* pool_out, int n, int e, int g) {
    const int* src = ei;
    const int* dst = ei + e;

    float *dG, *dHa, *dHb;
    cudaGetSymbolAddress((void**)&dG,  g_G);
    cudaGetSymbolAddress((void**)&dHa, g_Ha);
    cudaGetSymbolAddress((void**)&dHb, g_Hb);

    int tb = 256;
    k_zero<<<(n + tb - 1) / tb, tb>>>(n, g);
    k_degree<<<(e + tb - 1) / tb, tb>>>(dst, e);
    k_dinv<<<(n + tb - 1) / tb, tb>>>(n);
    k_scan<<<1, 1024>>>(n);
    k_fill<<<(e + tb - 1) / tb, tb>>>(src, dst, e);

    size_t smem = (128 * 128 + 64 * 128) * sizeof(float);
    int gemm_grid = (n + 63) / 64;
    int gath_grid = (n * 32 + tb - 1) / tb;

    // layer 1: Ha = relu(gcn(x, W1) + b1)
    k_gemm_big<<<gemm_grid, 256, smem>>>((const float4*)x, (const float4*)W1, (float4*)dG, n);
    k_gather<<<gath_grid, tb>>>((const float4*)dG, b1, nullptr, (float4*)dHa, n, 0);
    // layer 2: Hb = relu(gcn(Ha, W2) + b2) + Ha
    k_gemm_big<<<gemm_grid, 256, smem>>>((const float4*)dHa, (const float4*)W2, (float4*)dG, n);
    k_gather<<<gath_grid, tb>>>((const float4*)dG, b2, (const float4*)dHa, (float4*)dHb, n, 1);
    // layer 3: Ha = relu(gcn(Hb, W3) + b3) + Hb
    k_gemm_big<<<gemm_grid, 256, smem>>>((const float4*)dHb, (const float4*)W3, (float4*)dG, n);
    k_gather<<<gath_grid, tb>>>((const float4*)dG, b3, (const float4*)dHb, (float4*)dHa, n, 1);

    k_bounds<<<(n + tb - 1) / tb, tb>>>(batch, n);
    k_pool<<<(g * 32 + tb - 1) / tb, tb>>>((const float4*)dHa, (float4*)pool_out, g);
}

extern "C" void kernel_launch(void* const* d_in, const int* in_sizes, int n_in,
                              void* d_out, int out_size) {
    const float* x1  = (const float*)d_in[0];
    const int*   ei1 = (const int*)  d_in[1];
    const int*   bt1 = (const int*)  d_in[2];
    const float* x2  = (const float*)d_in[3];
    const int*   ei2 = (const int*)  d_in[4];
    const int*   bt2 = (const int*)  d_in[5];
    const float* W1  = (const float*)d_in[6];
    const float* b1  = (const float*)d_in[7];
    const float* W2  = (const float*)d_in[8];
    const float* b2  = (const float*)d_in[9];
    const float* W3  = (const float*)d_in[10];
    const float* b3  = (const float*)d_in[11];
    const float* Wp1 = (const float*)d_in[12];
    const float* bp1 = (const float*)d_in[13];
    const float* ga1 = (const float*)d_in[14];
    const float* be1 = (const float*)d_in[15];
    const float* Wp2 = (const float*)d_in[16];
    const float* bp2 = (const float*)d_in[17];
    const float* ga2 = (const float*)d_in[18];
    const float* be2 = (const float*)d_in[19];
    const float* Wq1 = (const float*)d_in[20];
    const float* bq1 = (const float*)d_in[21];
    const float* Wq2 = (const float*)d_in[22];
    const float* bq2 = (const float*)d_in[23];

    int n = in_sizes[0] / INF_;
    int e = in_sizes[1] / 2;
    int g = GG;

    cudaFuncSetAttribute(k_gemm_big, cudaFuncAttributeMaxDynamicSharedMemorySize,
                         (128 * 128 + 64 * 128) * sizeof(float));

    float *dPool, *dT, *dT2, *dQ;
    cudaGetSymbolAddress((void**)&dPool, g_pool);
    cudaGetSymbolAddress((void**)&dT,  g_t);
    cudaGetSymbolAddress((void**)&dT2, g_t2);
    cudaGetSymbolAddress((void**)&dQ,  g_q);

    run_encoder(x1, ei1, bt1, W1, b1, W2, b2, W3, b3, dPool,               n, e, g);
    run_encoder(x2, ei2, bt2, W1, b1, W2, b2, W3, b3, dPool + g * HID,     n, e, g);

    float* out = (float*)d_out;
    // output layout: p1 | p2 | z1 | z2, each [512, 256]
    for (int i = 0; i < 2; i++) {
        const float* hp = dPool + i * g * HID;
        float* zout = out + (2 + i) * g * PROJ;
        float* pout = out + i * g * PROJ;
        int gw_blocks = (g * 32 + 255) / 256;
        // projector
        k_gemm_small<8><<<gw_blocks, 256>>>(hp, Wp1, bp1, dT, g, HID, PROJ, 0);
        k_bn<<<PROJ, 128>>>(dT, ga1, be1, dT, g, PROJ, 1);
        k_gemm_small<8><<<gw_blocks, 256>>>(dT, Wp2, bp2, dT2, g, PROJ, PROJ, 0);
        k_bn<<<PROJ, 128>>>(dT2, ga2, be2, zout, g, PROJ, 0);
        // predictor
        k_gemm_small<4><<<gw_blocks, 256>>>(zout, Wq1, bq1, dQ, g, PROJ, PROJ / 2, 1);
        k_gemm_small<8><<<gw_blocks, 256>>>(dQ, Wq2, bq2, pout, g, PROJ / 2, PROJ, 0);
    }
}

// round 3
// speedup vs baseline: 1.2768x; 1.2768x over previous
#include <cuda_runtime.h>
#include <cuda_bf16.h>
#include <math.h>

// Problem constants
#define NN 50000
#define EE 1600000
#define GG 512
#define INF_ 128
#define HID 128
#define PROJ 256
#define NPART 128   // >= ceil(NN/512)

// ---------------- device scratch, duplicated per encoder ----------------
// NOTE: member order matters — every array cast to float4* must stay 16B
// aligned. All members except `off` have byte sizes that are multiples of 16;
// the odd-sized off[NN+1] therefore goes LAST.
struct alignas(16) EncScratch {
    float G [NN * HID];
    float Ha[NN * HID];
    float Hb[NN * HID];
    float pool[GG * HID];
    float t [GG * PROJ];
    float t2[GG * PROJ];
    float q [GG * (PROJ/2)];
    float dinv[NN];
    int   cnt[NN];
    int   csr[EE];
    int   gs[GG];
    int   ge[GG];
    int   part[NPART];
    int   off[NN + 1];        // odd size -> keep last
};
__device__ EncScratch g_e0;
__device__ EncScratch g_e1;

// ---------------- CSR build ----------------
__global__ void k_zero(int* cnt, int* gs, int* ge, int n, int g) {
    int i = blockIdx.x * blockDim.x + threadIdx.x;
    if (i < n) cnt[i] = 0;
    if (i < g) { gs[i] = n; ge[i] = 0; }
}

__global__ void k_degree(const int* __restrict__ dst, int* cnt, int e) {
    int i = blockIdx.x * blockDim.x + threadIdx.x;
    if (i < e) atomicAdd(&cnt[dst[i]], 1);
}

// block partial sums of cnt
__global__ void k_part(const int* __restrict__ cnt, int* part, int n) {
    __shared__ int red[16];
    int i = blockIdx.x * blockDim.x + threadIdx.x;
    int v = (i < n) ? cnt[i] : 0;
    int lane = threadIdx.x & 31, wid = threadIdx.x >> 5;
    #pragma unroll
    for (int o = 16; o; o >>= 1) v += __shfl_down_sync(0xffffffffu, v, o);
    if (lane == 0) red[wid] = v;
    __syncthreads();
    if (wid == 0) {
        int s = (lane < (blockDim.x >> 5)) ? red[lane] : 0;
        #pragma unroll
        for (int o = 16; o; o >>= 1) s += __shfl_down_sync(0xffffffffu, s, o);
        if (lane == 0) part[blockIdx.x] = s;
    }
}

// exclusive scan of nb partials (single small block)
__global__ void k_scanpart(int* part, int nb) {
    __shared__ int sh[NPART];
    int tid = threadIdx.x;
    sh[tid] = (tid < nb) ? part[tid] : 0;
    __syncthreads();
    for (int d = 1; d < NPART; d <<= 1) {
        int v = (tid >= d) ? sh[tid - d] : 0;
        __syncthreads();
        sh[tid] += v;
        __syncthreads();
    }
    if (tid < nb) part[tid] = (tid == 0) ? 0 : sh[tid - 1];
}

// per-element offsets + dinv + cursor init
__global__ void k_off(int* cnt, const int* __restrict__ part, int* off,
                      float* dinv, int n) {
    __shared__ int wsum[16];
    int i = blockIdx.x * blockDim.x + threadIdx.x;
    int lane = threadIdx.x & 31, wid = threadIdx.x >> 5;
    int nw = blockDim.x >> 5;
    int v = (i < n) ? cnt[i] : 0;
    int x = v;
    #pragma unroll
    for (int d = 1; d < 32; d <<= 1) {
        int y = __shfl_up_sync(0xffffffffu, x, d);
        if (lane >= d) x += y;
    }
    if (lane == 31) wsum[wid] = x;
    __syncthreads();
    if (wid == 0) {
        int s = (lane < nw) ? wsum[lane] : 0;
        #pragma unroll
        for (int d = 1; d < 32; d <<= 1) {
            int y = __shfl_up_sync(0xffffffffu, s, d);
            if (lane >= d) s += y;
        }
        wsum[lane] = s;
    }
    __syncthreads();
    int excl = x - v + ((wid == 0) ? 0 : wsum[wid - 1]) + part[blockIdx.x];
    if (i < n) {
        off[i]  = excl;
        dinv[i] = rsqrtf((float)(v + 1));
        cnt[i]  = excl;          // cursor for fill
        if (i == n - 1) off[n] = excl + v;
    }
}

__global__ void k_fill(const int* __restrict__ src, const int* __restrict__ dst,
                       int* cnt, int* csr, int e) {
    int i = blockIdx.x * blockDim.x + threadIdx.x;
    if (i < e) {
        int d = dst[i];
        int pos = atomicAdd(&cnt[d], 1);
        csr[pos] = src[i];
    }
}

// ---------------- big GEMM: out[M,128] = A[M,128] @ W[128,128] ----------------
__global__ __launch_bounds__(256) void k_gemm_big(
        const float4* __restrict__ A, const float4* __restrict__ W,
        float4* __restrict__ out, int M) {
    extern __shared__ float sm[];
    float4* Ws4 = (float4*)sm;                 // [128*32]
    float4* As4 = (float4*)(sm + 128 * 128);   // [64*32]
    const float* As = sm + 128 * 128;
    int tid = threadIdx.x;
    for (int i = tid; i < 128 * 32; i += 256) Ws4[i] = W[i];
    int rowbase = blockIdx.x * 64;
    for (int i = tid; i < 64 * 32; i += 256) {
        int r = rowbase + (i >> 5);
        float4 v = make_float4(0.f, 0.f, 0.f, 0.f);
        if (r < M) v = A[r * 32 + (i & 31)];
        As4[i] = v;
    }
    __syncthreads();
    int lane = tid & 31, w = tid >> 5;
    float4 acc[8];
    #pragma unroll
    for (int r = 0; r < 8; r++) acc[r] = make_float4(0.f, 0.f, 0.f, 0.f);
    #pragma unroll 8
    for (int k = 0; k < 128; k++) {
        float4 wv = Ws4[k * 32 + lane];
        #pragma unroll
        for (int r = 0; r < 8; r++) {
            float av = As[(w + r * 8) * 128 + k];
            acc[r].x += av * wv.x; acc[r].y += av * wv.y;
            acc[r].z += av * wv.z; acc[r].w += av * wv.w;
        }
    }
    #pragma unroll
    for (int r = 0; r < 8; r++) {
        int row = rowbase + w + r * 8;
        if (row < M) out[row * 32 + lane] = acc[r];
    }
}

// ---------------- gather: warp per node ----------------
__global__ void k_gather(const float4* __restrict__ B, const float* __restrict__ bias,
                         const float4* __restrict__ Hres, float4* __restrict__ out,
                         const int* __restrict__ off, const int* __restrict__ csr,
                         const float* __restrict__ dinv, int n, int mode) {
    int gw = (blockIdx.x * blockDim.x + threadIdx.x) >> 5;
    if (gw >= n) return;
    int lane = threadIdx.x & 31;
    int v = gw;
    int off0 = off[v], off1 = off[v + 1];
    float dv = dinv[v];
    float4 bv = B[v * 32 + lane];
    float4 acc = make_float4(dv * bv.x, dv * bv.y, dv * bv.z, dv * bv.w);
    for (int j = off0; j < off1; j += 32) {
        int idx = j + lane;
        int u = (idx < off1) ? csr[idx] : -1;
        float wt = (u >= 0) ? dinv[u] : 0.f;
        int m = off1 - j; if (m > 32) m = 32;
        #pragma unroll 4
        for (int i = 0; i < m; i++) {
            int uu = __shfl_sync(0xffffffffu, u, i);
            float ww = __shfl_sync(0xffffffffu, wt, i);
            float4 hv = B[uu * 32 + lane];
            acc.x += ww * hv.x; acc.y += ww * hv.y;
            acc.z += ww * hv.z; acc.w += ww * hv.w;
        }
    }
    const float4* b4 = (const float4*)bias;
    float4 bb = b4[lane];
    float4 r;
    r.x = fmaxf(dv * acc.x + bb.x, 0.f);
    r.y = fmaxf(dv * acc.y + bb.y, 0.f);
    r.z = fmaxf(dv * acc.z + bb.z, 0.f);
    r.w = fmaxf(dv * acc.w + bb.w, 0.f);
    if (mode == 1) {
        float4 h = Hres[v * 32 + lane];
        r.x += h.x; r.y += h.y; r.z += h.z; r.w += h.w;
    }
    out[v * 32 + lane] = r;
}

// ---------------- pooling ----------------
__global__ void k_bounds(const int* __restrict__ batch, int* gs, int* ge, int n) {
    int i = blockIdx.x * blockDim.x + threadIdx.x;
    if (i >= n) return;
    int b = batch[i];
    if (i == 0 || batch[i - 1] != b) gs[b] = i;
    if (i == n - 1 || batch[i + 1] != b) ge[b] = i + 1;
}

__global__ void k_pool(const float4* __restrict__ H, float4* __restrict__ pool,
                       const int* __restrict__ gs, const int* __restrict__ ge, int g) {
    int gw = (blockIdx.x * blockDim.x + threadIdx.x) >> 5;
    if (gw >= g) return;
    int lane = threadIdx.x & 31;
    int s = gs[gw], e = ge[gw];
    float4 acc = make_float4(0.f, 0.f, 0.f, 0.f);
    for (int r = s; r < e; r++) {
        float4 v = H[r * 32 + lane];
        acc.x += v.x; acc.y += v.y; acc.z += v.z; acc.w += v.w;
    }
    float sc = (e > s) ? 1.0f / (float)(e - s) : 0.f;
    pool[gw * 32 + lane] = make_float4(acc.x * sc, acc.y * sc, acc.z * sc, acc.w * sc);
}

// ---------------- small GEMM: warp per row ----------------
template <int NPER>
__global__ void k_gemm_small(const float* __restrict__ A, const float* __restrict__ W,
                             const float* __restrict__ bias, float* __restrict__ out,
                             int M, int K, int N, int relu) {
    int gw = (blockIdx.x * blockDim.x + threadIdx.x) >> 5;
    if (gw >= M) return;
    int lane = threadIdx.x & 31;
    float acc[NPER];
    #pragma unroll
    for (int j = 0; j < NPER; j++) acc[j] = 0.f;
    const float* a = A + gw * K;
    for (int k = 0; k < K; k++) {
        float av = __ldg(a + k);
        const float* wr = W + k * N;
        #pragma unroll
        for (int j = 0; j < NPER; j++) acc[j] += av * __ldg(wr + lane + 32 * j);
    }
    #pragma unroll
    for (int j = 0; j < NPER; j++) {
        float v = acc[j] + bias[lane + 32 * j];
        if (relu) v = fmaxf(v, 0.f);
        out[gw * N + lane + 32 * j] = v;
    }
}

// ---------------- batchnorm ----------------
__global__ void k_bn(const float* __restrict__ x, const float* __restrict__ gamma,
                     const float* __restrict__ beta, float* __restrict__ out,
                     int rows, int cols, int relu) {
    int col = blockIdx.x;
    int tid = threadIdx.x, lane = tid & 31, wid = tid >> 5;
    __shared__ float red[8];
    __shared__ float s_m, s_inv;
    float s = 0.f, s2 = 0.f;
    for (int r = tid; r < rows; r += blockDim.x) {
        float v = x[r * cols + col];
        s += v; s2 += v * v;
    }
    #pragma unroll
    for (int o = 16; o; o >>= 1) {
        s  += __shfl_down_sync(0xffffffffu, s, o);
        s2 += __shfl_down_sync(0xffffffffu, s2, o);
    }
    if (lane == 0) { red[wid] = s; red[4 + wid] = s2; }
    __syncthreads();
    if (tid == 0) {
        float ts = red[0] + red[1] + red[2] + red[3];
        float t2 = red[4] + red[5] + red[6] + red[7];
        float m = ts / rows;
        float var = t2 / rows - m * m;
        s_m = m;
        s_inv = rsqrtf(var + 1e-5f);
    }
    __syncthreads();
    float m = s_m, inv = s_inv, ga = gamma[col], be = beta[col];
    for (int r = tid; r < rows; r += blockDim.x) {
        float v = ga * (x[r * cols + col] - m) * inv + be;
        if (relu) v = fmaxf(v, 0.f);
        out[r * cols + col] = v;
    }
}

// ---------------- host orchestration ----------------
struct HeadW {
    const float *Wp1, *bp1, *ga1, *be1, *Wp2, *bp2, *ga2, *be2;
    const float *Wq1, *bq1, *Wq2, *bq2;
};

static void run_encoder_and_head(cudaStream_t st, EncScratch* S,
        const float* x, const int* ei, const int* batch,
        const float* W1, const float* b1, const float* W2, const float* b2,
        const float* W3, const float* b3, const HeadW& hw,
        float* pout, float* zout, int n, int e, int g) {
    const int* src = ei;
    const int* dst = ei + e;

    int tb = 256;
    int nb512 = (n + 511) / 512;
    k_zero  <<<(n + tb - 1) / tb, tb, 0, st>>>(S->cnt, S->gs, S->ge, n, g);
    k_degree<<<(e + tb - 1) / tb, tb, 0, st>>>(dst, S->cnt, e);
    k_part  <<<nb512, 512, 0, st>>>(S->cnt, S->part, n);
    k_scanpart<<<1, NPART, 0, st>>>(S->part, nb512);
    k_off   <<<nb512, 512, 0, st>>>(S->cnt, S->part, S->off, S->dinv, n);
    k_fill  <<<(e + tb - 1) / tb, tb, 0, st>>>(src, dst, S->cnt, S->csr, e);

    size_t smem = (128 * 128 + 64 * 128) * sizeof(float);
    int gemm_grid = (n + 63) / 64;
    int gath_grid = (n * 32 + tb - 1) / tb;

    float4* G  = (float4*)S->G;
    float4* Ha = (float4*)S->Ha;
    float4* Hb = (float4*)S->Hb;

    k_gemm_big<<<gemm_grid, 256, smem, st>>>((const float4*)x, (const float4*)W1, G, n);
    k_gather<<<gath_grid, tb, 0, st>>>(G, b1, nullptr, Ha, S->off, S->csr, S->dinv, n, 0);
    k_gemm_big<<<gemm_grid, 256, smem, st>>>((const float4*)Ha, (const float4*)W2, G, n);
    k_gather<<<gath_grid, tb, 0, st>>>(G, b2, (const float4*)Ha, Hb, S->off, S->csr, S->dinv, n, 1);
    k_gemm_big<<<gemm_grid, 256, smem, st>>>((const float4*)Hb, (const float4*)W3, G, n);
    k_gather<<<gath_grid, tb, 0, st>>>(G, b3, (const float4*)Hb, Ha, S->off, S->csr, S->dinv, n, 1);

    k_bounds<<<(n + tb - 1) / tb, tb, 0, st>>>(batch, S->gs, S->ge, n);
    k_pool<<<(g * 32 + tb - 1) / tb, tb, 0, st>>>((const float4*)Ha, (float4*)S->pool,
                                                  S->gs, S->ge, g);

    // head
    int gw_blocks = (g * 32 + 255) / 256;
    k_gemm_small<8><<<gw_blocks, 256, 0, st>>>(S->pool, hw.Wp1, hw.bp1, S->t, g, HID, PROJ, 0);
    k_bn<<<PROJ, 128, 0, st>>>(S->t, hw.ga1, hw.be1, S->t, g, PROJ, 1);
    k_gemm_small<8><<<gw_blocks, 256, 0, st>>>(S->t, hw.Wp2, hw.bp2, S->t2, g, PROJ, PROJ, 0);
    k_bn<<<PROJ, 128, 0, st>>>(S->t2, hw.ga2, hw.be2, zout, g, PROJ, 0);
    k_gemm_small<4><<<gw_blocks, 256, 0, st>>>(zout, hw.Wq1, hw.bq1, S->q, g, PROJ, PROJ / 2, 1);
    k_gemm_small<8><<<gw_blocks, 256, 0, st>>>(S->q, hw.Wq2, hw.bq2, pout, g, PROJ / 2, PROJ, 0);
}

extern "C" void kernel_launch(void* const* d_in, const int* in_sizes, int n_in,
                              void* d_out, int out_size) {
    const float* x1  = (const float*)d_in[0];
    const int*   ei1 = (const int*)  d_in[1];
    const int*   bt1 = (const int*)  d_in[2];
    const float* x2  = (const float*)d_in[3];
    const int*   ei2 = (const int*)  d_in[4];
    const int*   bt2 = (const int*)  d_in[5];
    const float* W1  = (const float*)d_in[6];
    const float* b1  = (const float*)d_in[7];
    const float* W2  = (const float*)d_in[8];
    const float* b2  = (const float*)d_in[9];
    const float* W3  = (const float*)d_in[10];
    const float* b3  = (const float*)d_in[11];
    HeadW hw;
    hw.Wp1 = (const float*)d_in[12]; hw.bp1 = (const float*)d_in[13];
    hw.ga1 = (const float*)d_in[14]; hw.be1 = (const float*)d_in[15];
    hw.Wp2 = (const float*)d_in[16]; hw.bp2 = (const float*)d_in[17];
    hw.ga2 = (const float*)d_in[18]; hw.be2 = (const float*)d_in[19];
    hw.Wq1 = (const float*)d_in[20]; hw.bq1 = (const float*)d_in[21];
    hw.Wq2 = (const float*)d_in[22]; hw.bq2 = (const float*)d_in[23];

    int n = in_sizes[0] / INF_;
    int e = in_sizes[1] / 2;
    int g = GG;

    static bool init = false;
    static cudaStream_t s2;
    static cudaEvent_t evFork, evJoin;
    if (!init) {
        cudaStreamCreateWithFlags(&s2, cudaStreamNonBlocking);
        cudaEventCreateWithFlags(&evFork, cudaEventDisableTiming);
        cudaEventCreateWithFlags(&evJoin, cudaEventDisableTiming);
        cudaFuncSetAttribute(k_gemm_big, cudaFuncAttributeMaxDynamicSharedMemorySize,
                             (128 * 128 + 64 * 128) * sizeof(float));
        init = true;
    }

    EncScratch *S0, *S1;
    cudaGetSymbolAddress((void**)&S0, g_e0);
    cudaGetSymbolAddress((void**)&S1, g_e1);

    float* out = (float*)d_out;
    float* p1 = out;
    float* p2 = out + g * PROJ;
    float* z1 = out + 2 * g * PROJ;
    float* z2 = out + 3 * g * PROJ;

    // fork
    cudaEventRecord(evFork, 0);
    cudaStreamWaitEvent(s2, evFork, 0);

    run_encoder_and_head(0,  S0, x1, ei1, bt1, W1, b1, W2, b2, W3, b3, hw, p1, z1, n, e, g);
    run_encoder_and_head(s2, S1, x2, ei2, bt2, W1, b1, W2, b2, W3, b3, hw, p2, z2, n, e, g);

    // join
    cudaEventRecord(evJoin, s2);
    cudaStreamWaitEvent(0, evJoin, 0);
}